// round 3
// baseline (speedup 1.0000x reference)
#include <cuda_runtime.h>
#include <math.h>

#define S_LEN  1024
#define B_SIZE 512
#define NTAG   48

__device__ float g_llh[B_SIZE];

__global__ void __launch_bounds__(64)
crf_forward_kernel(const float* __restrict__ emissions,
                   const int* __restrict__ tags,
                   const int* __restrict__ mask,
                   const float* __restrict__ start_t,
                   const float* __restrict__ end_t,
                   const float* __restrict__ trans)
{
    const int b    = blockIdx.x;
    const int j    = threadIdx.x;          // 0..63, tags are 0..47
    const int lane = j & 31;
    const int wid  = j >> 5;
    const bool act = (j < NTAG);

    __shared__ __align__(16) float v_sh[2][64];
    __shared__ float wred[2];
    __shared__ float red[4];

    // E column in registers: Ecol[i] = exp(T[i][j])
    float Ecol[NTAG];
#pragma unroll
    for (int i = 0; i < NTAG; i++)
        Ecol[i] = act ? __expf(trans[i * NTAG + j]) : 0.f;
    const float expEnd = act ? __expf(end_t[j]) : 0.f;

    // ---- t = 0 ----
    float em = act ? emissions[(size_t)b * NTAG + j] : -1e30f;
    const int tag0 = tags[b];
    float nm = 0.f;
    float score0 = (act ? start_t[j] : -1e30f) + em;
    if (j == tag0) nm = score0;
    v_sh[0][j] = act ? __expf(score0) : 0.f;
    v_sh[1][j] = 0.f;

    float M = 0.f;
    int prev_tag = tag0;
    int last_tag = tag0;
    int cur = 0;
    int nupd = 0;

    // prefetch t=1
    float em_next = act ? emissions[(size_t)(1 * B_SIZE + b) * NTAG + j] : -1e30f;
    __syncthreads();

    for (int t = 1; t < S_LEN; t++) {
        em = em_next;
        if (t + 1 < S_LEN)
            em_next = act ? emissions[(size_t)((t + 1) * B_SIZE + b) * NTAG + j] : -1e30f;
        const int tg  = tags[t * B_SIZE + b];
        const int m_t = mask[t * B_SIZE + b];

        const float e_em = __expf(em);   // starts early, overlaps dot

        // S[j] = sum_i v[i] * E[i][j]
        const float* vv = v_sh[cur];
        float s0 = 0.f, s1 = 0.f, s2 = 0.f, s3 = 0.f;
#pragma unroll
        for (int i = 0; i < NTAG; i += 4) {
            const float4 v4 = *(const float4*)(vv + i);
            s0 = fmaf(v4.x, Ecol[i + 0], s0);
            s1 = fmaf(v4.y, Ecol[i + 1], s1);
            s2 = fmaf(v4.z, Ecol[i + 2], s2);
            s3 = fmaf(v4.w, Ecol[i + 3], s3);
        }
        float w = ((s0 + s1) + (s2 + s3)) * e_em;

        if (m_t) {
            // fused numerator: lane matching the gold tag accumulates
            if (j == tg) nm += em + trans[prev_tag * NTAG + j];
            last_tag = tg;
            nupd++;
            if ((nupd & 7) == 0) {
                // renormalize: r = max_j w ; M += log r ; w /= r
                float r = w;
#pragma unroll
                for (int o = 16; o > 0; o >>= 1)
                    r = fmaxf(r, __shfl_xor_sync(0xffffffffu, r, o));
                if (lane == 0) wred[wid] = r;
                __syncthreads();
                r = fmaxf(fmaxf(wred[0], wred[1]), 1e-30f);
                M += __logf(r);
                w *= (1.f / r);
            }
            v_sh[cur ^ 1][j] = w;
        }
        prev_tag = tg;
        __syncthreads();
        if (m_t) cur ^= 1;
    }

    // ---- finalize ----
    float contrib = v_sh[cur][j] * expEnd;   // 0 for j>=48
    float nsum = nm;
#pragma unroll
    for (int o = 16; o > 0; o >>= 1) {
        contrib += __shfl_xor_sync(0xffffffffu, contrib, o);
        nsum    += __shfl_xor_sync(0xffffffffu, nsum, o);
    }
    if (lane == 0) { red[wid] = contrib; red[wid + 2] = nsum; }
    __syncthreads();
    if (j == 0) {
        const float denom = M + __logf(red[0] + red[1]);
        const float numer = red[2] + red[3] + end_t[last_tag];
        g_llh[b] = numer - denom;
    }
}

__global__ void __launch_bounds__(512)
crf_reduce_kernel(float* __restrict__ out)
{
    __shared__ float sh[512];
    const int t = threadIdx.x;
    sh[t] = g_llh[t];
    __syncthreads();
#pragma unroll
    for (int o = 256; o > 0; o >>= 1) {
        if (t < o) sh[t] += sh[t + o];
        __syncthreads();
    }
    if (t == 0) out[0] = sh[0] * (1.f / (float)B_SIZE);
}

extern "C" void kernel_launch(void* const* d_in, const int* in_sizes, int n_in,
                              void* d_out, int out_size)
{
    const float* emissions = (const float*)d_in[0];
    const int*   tags      = (const int*)d_in[1];
    const int*   mask      = (const int*)d_in[2];
    const float* start_t   = (const float*)d_in[3];
    const float* end_t     = (const float*)d_in[4];
    const float* trans     = (const float*)d_in[5];

    crf_forward_kernel<<<B_SIZE, 64>>>(emissions, tags, mask, start_t, end_t, trans);
    crf_reduce_kernel<<<1, 512>>>((float*)d_out);
}

// round 6
// speedup vs baseline: 2.7791x; 2.7791x over previous
#include <cuda_runtime.h>
#include <math.h>

#define S_LEN  1024
#define B_SIZE 512
#define NTAG   48
#define PF     4

__device__ float g_den[B_SIZE];
__device__ float g_num[B_SIZE];

__device__ __forceinline__ unsigned long long pack2f(float lo, float hi) {
    unsigned long long r;
    asm("mov.b64 %0, {%1, %2};" : "=l"(r) : "f"(lo), "f"(hi));
    return r;
}
__device__ __forceinline__ void unpack2f(unsigned long long v, float& lo, float& hi) {
    asm("mov.b64 {%0, %1}, %2;" : "=f"(lo), "=f"(hi) : "l"(v));
}
__device__ __forceinline__ void ffma2(unsigned long long& acc,
                                      unsigned long long a, unsigned long long b) {
    asm("fma.rn.f32x2 %0, %1, %2, %0;" : "+l"(acc) : "l"(a), "l"(b));
}

// ---------------- forward (denominator) kernel: one warp per chain ----------------
__global__ void __launch_bounds__(32)
crf_fwd_kernel(const float* __restrict__ emissions,
               const int* __restrict__ mask,
               const float* __restrict__ start_t,
               const float* __restrict__ end_t,
               const float* __restrict__ trans)
{
    const int b  = blockIdx.x;
    const int l  = threadIdx.x;       // 0..31
    const int j0 = l;                 // cols 0..31
    const int j1 = l + 32;            // cols 32..63 (48..63 dummy)
    const bool a1 = (j1 < NTAG);      // l < 16

    __shared__ __align__(16) float2 sh2[64];   // duplicated v: sh2[i] = {v_i, v_i}

    // packed E columns: E2[i] = { exp(T[i][j0]), exp(T[i][j1]) }
    unsigned long long E2[NTAG];
#pragma unroll
    for (int i = 0; i < NTAG; i++) {
        float e0 = __expf(trans[i * NTAG + j0]);
        float e1 = a1 ? __expf(trans[i * NTAG + j1]) : 0.f;
        E2[i] = pack2f(e0, e1);
    }

    // ---- t = 0 ----
    float em0 = emissions[(size_t)b * NTAG + j0];
    float em1 = a1 ? emissions[(size_t)b * NTAG + j1] : 0.f;
    float s1i = a1 ? start_t[j1] : -1e30f;
    float w0 = __expf(start_t[j0] + em0);
    float w1 = a1 ? __expf(s1i + em1) : 0.f;
    sh2[j0] = make_float2(w0, w0);
    sh2[j1] = make_float2(w1, w1);

    // prefetch ring for emissions, depth PF
    float pf0[PF], pf1[PF];
#pragma unroll
    for (int k = 0; k < PF; k++) {
        int t = 1 + k;
        pf0[(t) & (PF - 1)] = emissions[((size_t)t * B_SIZE + b) * NTAG + j0];
        pf1[(t) & (PF - 1)] = a1 ? emissions[((size_t)t * B_SIZE + b) * NTAG + j1] : 0.f;
    }

    // mask bits for t in [0,32)
    unsigned mbits;
    {
        int mt = mask[(size_t)l * B_SIZE + b];
        mbits = __ballot_sync(0xffffffffu, mt != 0);
    }
    __syncwarp();

    float M = 0.f;
    int nupd = 0;

#pragma unroll 4
    for (int t = 1; t < S_LEN; t++) {
        if ((t & 31) == 0) {
            int mt = mask[(size_t)(t + l) * B_SIZE + b];
            mbits = __ballot_sync(0xffffffffu, mt != 0);
        }
        const int m_t = (mbits >> (t & 31)) & 1;

        const int slot = t & (PF - 1);
        const float e0 = __expf(pf0[slot]);
        const float e1 = __expf(pf1[slot]);
        int tn = t + PF; if (tn >= S_LEN) tn = S_LEN - 1;   // harmless clamp
        pf0[slot] = emissions[((size_t)tn * B_SIZE + b) * NTAG + j0];
        pf1[slot] = a1 ? emissions[((size_t)tn * B_SIZE + b) * NTAG + j1] : 0.f;

        // packed matvec: acc = sum_i {v_i,v_i} * {E[i][j0],E[i][j1]}
        unsigned long long acc[6] = {0ull, 0ull, 0ull, 0ull, 0ull, 0ull};
        const ulonglong2* vp = (const ulonglong2*)sh2;
#pragma unroll
        for (int i = 0; i < NTAG; i += 2) {
            ulonglong2 v2 = vp[i >> 1];
            ffma2(acc[(i >> 1) % 6], v2.x, E2[i]);
            ffma2(acc[((i >> 1) + 3) % 6], v2.y, E2[i + 1]);
        }
        float s0 = 0.f, s1 = 0.f;
#pragma unroll
        for (int k = 0; k < 6; k++) {
            float lo, hi; unpack2f(acc[k], lo, hi);
            s0 += lo; s1 += hi;
        }
        float nw0 = s0 * e0;
        float nw1 = s1 * e1;   // 0 for dummy cols (E2 hi = 0)

        if (m_t) {             // uniform across warp
            w0 = nw0; w1 = nw1;
            nupd++;
            if ((nupd & 7) == 0) {
                float r = fmaxf(w0, w1);
#pragma unroll
                for (int o = 16; o > 0; o >>= 1)
                    r = fmaxf(r, __shfl_xor_sync(0xffffffffu, r, o));
                r = fmaxf(r, 1e-30f);
                M += __logf(r);
                float inv = 1.f / r;
                w0 *= inv; w1 *= inv;
            }
            sh2[j0] = make_float2(w0, w0);
            sh2[j1] = make_float2(w1, w1);
        }
        __syncwarp();
    }

    // ---- finalize denominator ----
    float ee0 = __expf(end_t[j0]);
    float ee1 = a1 ? __expf(end_t[j1]) : 0.f;
    float c = w0 * ee0 + w1 * ee1;
#pragma unroll
    for (int o = 16; o > 0; o >>= 1)
        c += __shfl_xor_sync(0xffffffffu, c, o);
    if (l == 0) g_den[b] = M + __logf(c);
}

// ---------------- numerator kernel: fully parallel gather ----------------
__global__ void __launch_bounds__(128)
crf_num_kernel(const float* __restrict__ emissions,
               const int* __restrict__ tags,
               const int* __restrict__ mask,
               const float* __restrict__ start_t,
               const float* __restrict__ end_t,
               const float* __restrict__ trans)
{
    const int b   = blockIdx.x;
    const int tid = threadIdx.x;
    const int lane = tid & 31;
    const int wid  = tid >> 5;

    float acc = 0.f;
    int cnt = 0;
    for (int t = tid; t < S_LEN; t += 128) {
        int tg = tags[t * B_SIZE + b];
        int m  = mask[t * B_SIZE + b];
        cnt += m;
        if (t == 0) {
            acc += start_t[tg] + emissions[(size_t)b * NTAG + tg];
        } else {
            int tp = tags[(t - 1) * B_SIZE + b];
            acc += (trans[tp * NTAG + tg] +
                    emissions[((size_t)t * B_SIZE + b) * NTAG + tg]) * (float)m;
        }
    }
#pragma unroll
    for (int o = 16; o > 0; o >>= 1) {
        acc += __shfl_xor_sync(0xffffffffu, acc, o);
        cnt += __shfl_xor_sync(0xffffffffu, cnt, o);
    }
    __shared__ float sacc[4];
    __shared__ int   scnt[4];
    if (lane == 0) { sacc[wid] = acc; scnt[wid] = cnt; }
    __syncthreads();
    if (tid == 0) {
        float total = sacc[0] + sacc[1] + sacc[2] + sacc[3];
        int   ctot  = scnt[0] + scnt[1] + scnt[2] + scnt[3];
        int seq_end = ctot - 1;
        int lt = tags[seq_end * B_SIZE + b];
        g_num[b] = total + end_t[lt];
    }
}

// ---------------- final reduce ----------------
__global__ void __launch_bounds__(512)
crf_reduce_kernel(float* __restrict__ out)
{
    __shared__ float sh[512];
    const int t = threadIdx.x;
    sh[t] = g_num[t] - g_den[t];
    __syncthreads();
#pragma unroll
    for (int o = 256; o > 0; o >>= 1) {
        if (t < o) sh[t] += sh[t + o];
        __syncthreads();
    }
    if (t == 0) out[0] = sh[0] * (1.f / (float)B_SIZE);
}

extern "C" void kernel_launch(void* const* d_in, const int* in_sizes, int n_in,
                              void* d_out, int out_size)
{
    const float* emissions = (const float*)d_in[0];
    const int*   tags      = (const int*)d_in[1];
    const int*   mask      = (const int*)d_in[2];
    const float* start_t   = (const float*)d_in[3];
    const float* end_t     = (const float*)d_in[4];
    const float* trans     = (const float*)d_in[5];

    crf_num_kernel<<<B_SIZE, 128>>>(emissions, tags, mask, start_t, end_t, trans);
    crf_fwd_kernel<<<B_SIZE, 32>>>(emissions, mask, start_t, end_t, trans);
    crf_reduce_kernel<<<1, 512>>>((float*)d_out);
}